// round 12
// baseline (speedup 1.0000x reference)
#include <cuda_runtime.h>
#include <cuda_bf16.h>

#define GDIM 128
#define NRAYS 2048
#define NSAMP 128
#define VD 28
#define BTHREADS 256
#define BWARPS 8
#define SAMP_PER_WARP (NSAMP / BWARPS)   // 16

// Offsets in float2 units (grid viewed as float2). Cell record = 28 floats =
// 14 float2. Valid because positions lie in [0, G-2): clamps are identity.
#define DY2 (GDIM * VD / 2)              // 1792
#define DX2 (GDIM * GDIM * VD / 2)       // 229376

// SH constants
#define Y00f 0.28209479177387814f
#define H3f  0.4886025119029199f
#define H15f 1.0925484305920792f
#define Q5f  0.31539156525252005f
#define Q15f 0.5462742152960396f

__global__ __launch_bounds__(BTHREADS, 6) void plenoxel_kernel(
    const float* __restrict__ grid,   // (G,G,G,28)
    const float* __restrict__ pos,    // (R,S,3)
    const float* __restrict__ dist,   // (R,S)
    const float* __restrict__ ang,    // (R,2)
    float* __restrict__ out)          // (R,3)
{
    const int r    = blockIdx.x;
    const int tid  = threadIdx.x;
    const int lane = tid & 31;
    const int wid  = tid >> 5;

    __shared__ float spos[NSAMP * 3];
    __shared__ float sdist[NSAMP];
    __shared__ float Ysh[9];
    __shared__ float att_s[NSAMP];
    __shared__ float rgb_s[NSAMP][3];
    __shared__ float warp_att[4];
    __shared__ float warp_rgb[4][3];

    // Stage per-ray sample data coalesced
    for (int i = tid; i < NSAMP * 3; i += BTHREADS)
        spos[i] = pos[r * NSAMP * 3 + i];
    for (int i = tid; i < NSAMP; i += BTHREADS)
        sdist[i] = dist[r * NSAMP + i];
    if (tid == 0) {
        float th = ang[2 * r + 0];
        float ph = ang[2 * r + 1];
        float st, ct, sp, cp;
        sincosf(th, &st, &ct);
        sincosf(ph, &sp, &cp);
        float stcp = st * cp;
        float stsp = st * sp;
        Ysh[0] = Y00f;
        Ysh[1] = H3f * stsp;
        Ysh[2] = H3f * ct;
        Ysh[3] = H3f * stcp;
        Ysh[4] = H15f * stcp * stsp;
        Ysh[5] = H15f * stsp * ct;
        Ysh[6] = Q5f * (3.0f * ct * ct - 1.0f);
        Ysh[7] = H15f * stcp * ct;
        Ysh[8] = Q15f * (stcp * stcp - stsp * stsp);
    }
    __syncthreads();

    // Per-lane SH coefficient; lane = feature channel (after redistribution).
    const bool act = (lane >= 1 && lane < VD);
    const int  j   = act ? (lane - 1) % 9 : 9;
    const int  g   = act ? (lane - 1) / 9 : 0;
    float ycoef = 0.0f;
    if (act) ycoef = Ysh[j];

    // Guards for the segmented 9-wide reduction tree (offsets 8,4,2,1)
    const bool p8 = act && (j == 0);
    const bool p4 = act && (j < 4);
    const bool p2 = act && (j < 2);
    const bool p1 = act && (j == 0);
    const bool pstore = act && (j == 0);   // lanes 1,10,19 hold final sums

    // float2-load lane: lane l (clamped to 27) loads float2 element l of the
    // 224-byte z-pair block. l<14 -> corner z (channels 2l,2l+1); l>=14 ->
    // corner z+1 (channels 2l-28, 2l-27).
    const int l2 = min(lane, VD - 1);
    const int src = lane >> 1;             // redistribution source lane
    const bool oddc = (lane & 1);

    const float2* __restrict__ grid2 = (const float2*)grid;

    // ---- Gather pass: two samples per iteration, 8 LDG.64 in flight ----
#pragma unroll
    for (int i = 0; i < SAMP_PER_WARP; i += 2) {
        const int s0 = wid * SAMP_PER_WARP + i;
        const int s1 = s0 + 1;

        const float pxA = spos[3 * s0 + 0], pyA = spos[3 * s0 + 1], pzA = spos[3 * s0 + 2];
        const float pxB = spos[3 * s1 + 0], pyB = spos[3 * s1 + 1], pzB = spos[3 * s1 + 2];

        const int ixA = (int)floorf(pxA), iyA = (int)floorf(pyA), izA = (int)floorf(pzA);
        const float fxA = pxA - (float)ixA, fyA = pyA - (float)iyA, fzA = pzA - (float)izA;
        const int ixB = (int)floorf(pxB), iyB = (int)floorf(pyB), izB = (int)floorf(pzB);
        const float fxB = pxB - (float)ixB, fyB = pyB - (float)iyB, fzB = pzB - (float)izB;

        // Base in float2 units: cell*14 + l2
        const int baseA = ((ixA * GDIM + iyA) * GDIM + izA) * (VD / 2) + l2;
        const int baseB = ((ixB * GDIM + iyB) * GDIM + izB) * (VD / 2) + l2;

        // --- 8 LDG.64 back-to-back; offsets are immediates ---
        const float2* gA = grid2 + baseA;
        const float2* gB = grid2 + baseB;
        const float2 a00 = __ldg(gA);                 // (x0,y0) z-pair
        const float2 a01 = __ldg(gA + DY2);           // (x0,y1)
        const float2 a10 = __ldg(gA + DX2);           // (x1,y0)
        const float2 a11 = __ldg(gA + DX2 + DY2);     // (x1,y1)
        const float2 b00 = __ldg(gB);
        const float2 b01 = __ldg(gB + DY2);
        const float2 b10 = __ldg(gB + DX2);
        const float2 b11 = __ldg(gB + DX2 + DY2);

        // --- xy-combine per component, then per-lane z weight ---
        const float wy0A = 1.0f - fyA, wy1A = fyA;
        const float wx0A = 1.0f - fxA, wx1A = fxA;
        const float wy0B = 1.0f - fyB, wy1B = fyB;
        const float wx0B = 1.0f - fxB, wx1B = fxB;
        const float wzA = (lane < 14) ? (1.0f - fzA) : fzA;
        const float wzB = (lane < 14) ? (1.0f - fzB) : fzB;

        float tAx = wx0A * (wy0A * a00.x + wy1A * a01.x)
                  + wx1A * (wy0A * a10.x + wy1A * a11.x);
        float tAy = wx0A * (wy0A * a00.y + wy1A * a01.y)
                  + wx1A * (wy0A * a10.y + wy1A * a11.y);
        float tBx = wx0B * (wy0B * b00.x + wy1B * b01.x)
                  + wx1B * (wy0B * b10.x + wy1B * b11.x);
        float tBy = wx0B * (wy0B * b00.y + wy1B * b01.y)
                  + wx1B * (wy0B * b10.y + wy1B * b11.y);
        tAx *= wzA;  tAy *= wzA;
        tBx *= wzB;  tBy *= wzB;

        // --- z-merge: lane l<14 adds lane l+14 (z+1 part, same channels) ---
        tAx += __shfl_down_sync(0xffffffffu, tAx, 14);
        tAy += __shfl_down_sync(0xffffffffu, tAy, 14);
        tBx += __shfl_down_sync(0xffffffffu, tBx, 14);
        tBy += __shfl_down_sync(0xffffffffu, tBy, 14);

        // --- redistribute to lane = channel: lane c takes comp (c&1) of lane c>>1 ---
        const float rAx = __shfl_sync(0xffffffffu, tAx, src);
        const float rAy = __shfl_sync(0xffffffffu, tAy, src);
        const float rBx = __shfl_sync(0xffffffffu, tBx, src);
        const float rBy = __shfl_sync(0xffffffffu, tBy, src);
        const float featsA = oddc ? rAy : rAx;
        const float featsB = oddc ? rBy : rBx;

        // att from channel 0
        const float sigmaA = __shfl_sync(0xffffffffu, featsA, 0);
        const float sigmaB = __shfl_sync(0xffffffffu, featsB, 0);
        if (lane == 0) {
            att_s[s0] = __expf(-sigmaA * sdist[s0]);
            att_s[s1] = __expf(-sigmaB * sdist[s1]);
        }

        // Segmented reduction: three 9-wide groups (lanes 1-9,10-18,19-27)
        float tA = featsA * ycoef;
        float tB = featsB * ycoef;
        float uA, uB;
        uA = __shfl_down_sync(0xffffffffu, tA, 8);
        uB = __shfl_down_sync(0xffffffffu, tB, 8);
        if (p8) { tA += uA; tB += uB; }
        uA = __shfl_down_sync(0xffffffffu, tA, 4);
        uB = __shfl_down_sync(0xffffffffu, tB, 4);
        if (p4) { tA += uA; tB += uB; }
        uA = __shfl_down_sync(0xffffffffu, tA, 2);
        uB = __shfl_down_sync(0xffffffffu, tB, 2);
        if (p2) { tA += uA; tB += uB; }
        uA = __shfl_down_sync(0xffffffffu, tA, 1);
        uB = __shfl_down_sync(0xffffffffu, tB, 1);
        if (p1) { tA += uA; tB += uB; }
        if (pstore) {
            rgb_s[s0][g] = tA;               // lanes 1,10,19 -> R,G,B
            rgb_s[s1][g] = tB;
        }
    }
    __syncthreads();

    // ---- 128-wide inclusive scan of att -> weight; reduce weighted rgb ----
    float x = 0.0f, att = 0.0f;
    if (tid < NSAMP) {
        att = att_s[tid];
        x   = att;
    }
#pragma unroll
    for (int o = 1; o < 32; o <<= 1) {
        float ysh = __shfl_up_sync(0xffffffffu, x, o);
        if (lane >= o) x += ysh;
    }
    if (tid < NSAMP && lane == 31) warp_att[wid] = x;
    __syncthreads();

    float vr = 0.0f, vg = 0.0f, vb = 0.0f;
    if (tid < NSAMP) {
        float offset = 0.0f;
#pragma unroll
        for (int i = 0; i < 3; i++)
            if (i < wid) offset += warp_att[i];
        const float trans  = x + offset;
        const float weight = trans * (1.0f - att);
        vr = weight * rgb_s[tid][0];
        vg = weight * rgb_s[tid][1];
        vb = weight * rgb_s[tid][2];
    }
#pragma unroll
    for (int o = 16; o > 0; o >>= 1) {
        vr += __shfl_down_sync(0xffffffffu, vr, o);
        vg += __shfl_down_sync(0xffffffffu, vg, o);
        vb += __shfl_down_sync(0xffffffffu, vb, o);
    }
    if (tid < NSAMP && lane == 0) {
        warp_rgb[wid][0] = vr;
        warp_rgb[wid][1] = vg;
        warp_rgb[wid][2] = vb;
    }
    __syncthreads();

    if (tid == 0) {
        float R = 0.0f, Gg = 0.0f, B = 0.0f;
#pragma unroll
        for (int i = 0; i < 4; i++) {
            R  += warp_rgb[i][0];
            Gg += warp_rgb[i][1];
            B  += warp_rgb[i][2];
        }
        out[3 * r + 0] = R;
        out[3 * r + 1] = Gg;
        out[3 * r + 2] = B;
    }
}

extern "C" void kernel_launch(void* const* d_in, const int* in_sizes, int n_in,
                              void* d_out, int out_size) {
    const float* grid = (const float*)d_in[0];
    const float* pos  = (const float*)d_in[1];
    const float* dst  = (const float*)d_in[2];
    const float* ang  = (const float*)d_in[3];
    float* out = (float*)d_out;
    plenoxel_kernel<<<NRAYS, BTHREADS>>>(grid, pos, dst, ang, out);
}